// round 1
// baseline (speedup 1.0000x reference)
#include <cuda_runtime.h>
#include <cuda_bf16.h>
#include <math_constants.h>
#include <cstdint>

// Shapes (fixed by the problem)
#define Bq 4
#define Tq 1024
#define Cq 16
#define Dq 256
#define NHEADS (Bq*Cq)          // 64
#define MTOT (Bq*Tq*Cq)         // 65536 tokens

// Scratch: q,k,v in head-major [B*C, T, D] layout (fp32)
__device__ float g_q[NHEADS * Tq * Dq];
__device__ float g_k[NHEADS * Tq * Dq];
__device__ float g_v[NHEADS * Tq * Dq];

// ---------------------------------------------------------------------------
// Kernel 1: fused QKV projection + bias + rotation (RoPE w/ table), writes
// q,k (rotated) and v into head-major scratch.
// GEMM: C[m][n] = sum_k x[m][k] * W[n][k],  M=65536, N=768 (q|k|v), K=256
// Block tile 64(M) x 64(N), K-step 16, 256 threads, 4x4 register micro-tile.
// ---------------------------------------------------------------------------
__global__ __launch_bounds__(256) void qkv_rope_kernel(
    const float* __restrict__ x,
    const int*   __restrict__ pos,
    const float* __restrict__ pe,
    const float* __restrict__ wq, const float* __restrict__ bq,
    const float* __restrict__ wk, const float* __restrict__ bk,
    const float* __restrict__ wv, const float* __restrict__ bv)
{
    __shared__ float As[16 * 64];
    __shared__ float Bs[16 * 64];

    const int tid = threadIdx.x;
    const int tx = tid & 15;
    const int ty = tid >> 4;
    const int bm = blockIdx.y * 64;
    const int bnb = blockIdx.x;        // 0..11
    const int mat = bnb >> 2;          // 0:q 1:k 2:v
    const int n0 = (bnb & 3) * 64;     // col offset within one 256-wide matrix

    const float* w    = (mat == 0) ? wq : (mat == 1) ? wk : wv;
    const float* bias = (mat == 0) ? bq : (mat == 1) ? bk : bv;

    float acc[4][4];
#pragma unroll
    for (int i = 0; i < 4; ++i)
#pragma unroll
        for (int j = 0; j < 4; ++j) acc[i][j] = 0.f;

    const int lrow = tid & 63;
    const int kq = tid >> 6;           // 0..3

    const float* xrow = x + (size_t)(bm + lrow) * Dq + kq * 4;
    const float* wrow = w + (size_t)(n0 + lrow) * Dq + kq * 4;

    for (int k0 = 0; k0 < Dq; k0 += 16) {
        float4 av = *(const float4*)(xrow + k0);
        float4 bvv = *(const float4*)(wrow + k0);
        __syncthreads();
        As[(kq*4+0)*64 + lrow] = av.x;
        As[(kq*4+1)*64 + lrow] = av.y;
        As[(kq*4+2)*64 + lrow] = av.z;
        As[(kq*4+3)*64 + lrow] = av.w;
        Bs[(kq*4+0)*64 + lrow] = bvv.x;
        Bs[(kq*4+1)*64 + lrow] = bvv.y;
        Bs[(kq*4+2)*64 + lrow] = bvv.z;
        Bs[(kq*4+3)*64 + lrow] = bvv.w;
        __syncthreads();
#pragma unroll
        for (int kk = 0; kk < 16; ++kk) {
            float4 a = *(const float4*)&As[kk*64 + ty*4];
            float4 b = *(const float4*)&Bs[kk*64 + tx*4];
            float ar[4] = {a.x, a.y, a.z, a.w};
            float br[4] = {b.x, b.y, b.z, b.w};
#pragma unroll
            for (int i = 0; i < 4; ++i)
#pragma unroll
                for (int j = 0; j < 4; ++j)
                    acc[i][j] += ar[i] * br[j];
        }
    }

    const int nloc = n0 + tx * 4;                     // 0..252, multiple of 4 (even pairs)
    const float4 bb = *(const float4*)(bias + nloc);
    float* outbuf = (mat == 0) ? g_q : (mat == 1) ? g_k : g_v;

#pragma unroll
    for (int i = 0; i < 4; ++i) {
        const int m = bm + ty*4 + i;
        const int b = m >> 14;                        // / (T*C)
        const int t = (m >> 4) & (Tq - 1);
        const int c = m & (Cq - 1);
        float4 r;
        r.x = acc[i][0] + bb.x;
        r.y = acc[i][1] + bb.y;
        r.z = acc[i][2] + bb.z;
        r.w = acc[i][3] + bb.w;
        if (mat < 2) {
            const int p = pos[m];
            const float4 cs = *(const float4*)(pe + (size_t)p * Dq + nloc);
            // pairs (nloc,nloc+1) and (nloc+2,nloc+3): (cos,sin)=(cs.x,cs.y),(cs.z,cs.w)
            float o0 = r.x * cs.x - r.y * cs.y;
            float o1 = r.x * cs.y + r.y * cs.x;
            float o2 = r.z * cs.z - r.w * cs.w;
            float o3 = r.z * cs.w + r.w * cs.z;
            r = make_float4(o0, o1, o2, o3);
        }
        *(float4*)(outbuf + ((size_t)((b * Cq + c) * Tq + t)) * Dq + nloc) = r;
    }
}

// ---------------------------------------------------------------------------
// Kernel 2: fused flash attention + residual + LayerScale + LayerNorm.
// One block per (head, 64-row q-tile). 256 threads: thread = (r, c4),
// r = tid>>2 owns q-row r, c4 = tid&3 owns interleaved column quads
// cols = c4*4 + g*16 + [0..3] for g in 0..15  (conflict-free K/V LDS.128).
// ---------------------------------------------------------------------------
#define SQ_STRIDE 260   // floats per sQ row (pad vs 256)
#define SS_STRIDE 33

__global__ __launch_bounds__(256, 1) void attn_ln_kernel(
    const float* __restrict__ x,
    const unsigned char* __restrict__ xmask,
    const float* __restrict__ lng,
    const float* __restrict__ lnb,
    const float* __restrict__ lsg,
    float* __restrict__ out)
{
    extern __shared__ float sm[];
    float* sQ = sm;                         // 64 * 260
    float* sK = sQ + 64 * SQ_STRIDE;        // 32 * 256
    float* sV = sK + 32 * 256;              // 32 * 256
    float* sS = sV + 32 * 256;              // 64 * 33
    int*   sQm = (int*)(sS + 64 * SS_STRIDE);  // 64
    int*   sKm = sQm + 64;                     // 32

    const int tid = threadIdx.x;
    const int qt = blockIdx.x;              // 0..15
    const int h  = blockIdx.y;              // 0..63
    const int b = h >> 4, c = h & 15;
    const int q0 = qt * 64;

    const int r  = tid >> 2;                // q-row within tile
    const int c4 = tid & 3;                 // column-quad group

    // ---- load Q tile (64 x 256) ----
    const float* qbase = g_q + ((size_t)h * Tq + q0) * Dq;
#pragma unroll
    for (int u = 0; u < 16; ++u) {
        int fidx = u * 256 + tid;           // 0..4095 float4 slots
        int row = fidx >> 6;
        int f = fidx & 63;
        *(float4*)(sQ + row * SQ_STRIDE + f * 4) =
            *(const float4*)(qbase + (size_t)row * Dq + f * 4);
    }
    if (tid < 64) {
        int t = q0 + tid;
        sQm[tid] = xmask[(b * Tq + t) * Cq + c];
    }
    __syncthreads();
    const int qm = sQm[r];

    float4 o4[16];
#pragma unroll
    for (int g = 0; g < 16; ++g) o4[g] = make_float4(0.f, 0.f, 0.f, 0.f);
    float mrun = -CUDART_INF_F;
    float lsum = 0.f;

    const float* kbase = g_k + (size_t)h * Tq * Dq;
    const float* vbase = g_v + (size_t)h * Tq * Dq;

    for (int kt = 0; kt < 32; ++kt) {
        const int k0 = kt * 32;
        __syncthreads();
        // load K,V tile (32 x 256 each)
#pragma unroll
        for (int u = 0; u < 8; ++u) {
            int fidx = u * 256 + tid;       // 0..2047
            int row = fidx >> 6;
            int f = fidx & 63;
            *(float4*)(sK + row * 256 + f * 4) =
                *(const float4*)(kbase + (size_t)(k0 + row) * Dq + f * 4);
            *(float4*)(sV + row * 256 + f * 4) =
                *(const float4*)(vbase + (size_t)(k0 + row) * Dq + f * 4);
        }
        if (tid < 32) sKm[tid] = xmask[(b * Tq + k0 + tid) * Cq + c];
        __syncthreads();

        // ---- S = Q K^T (partial per c4-lane, then 4-lane shuffle reduce) ----
        float s[32];
#pragma unroll
        for (int j = 0; j < 32; ++j) s[j] = 0.f;
        for (int g = 0; g < 16; ++g) {
            const float4 qv = *(const float4*)(sQ + r * SQ_STRIDE + (g * 4 + c4) * 4);
#pragma unroll
            for (int j = 0; j < 32; ++j) {
                const float4 kv = *(const float4*)(sK + j * 256 + (g * 4 + c4) * 4);
                s[j] += qv.x * kv.x + qv.y * kv.y + qv.z * kv.z + qv.w * kv.w;
            }
        }
        float tmax = -CUDART_INF_F;
#pragma unroll
        for (int j = 0; j < 32; ++j) {
            float v = s[j];
            v += __shfl_xor_sync(0xffffffffu, v, 1);
            v += __shfl_xor_sync(0xffffffffu, v, 2);
            v = (qm | sKm[j]) ? -CUDART_INF_F : v * 0.0625f;   // 1/sqrt(256)
            s[j] = v;
            tmax = fmaxf(tmax, v);
        }
        if (c4 == 0) {
#pragma unroll
            for (int j = 0; j < 32; ++j) sS[r * SS_STRIDE + j] = s[j];
        }
        __syncwarp();

        // ---- online softmax + PV ----
        if (tmax > -CUDART_INF_F) {
            const float mnew = fmaxf(mrun, tmax);
            const float corr = __expf(mrun - mnew);   // exp(-inf)=0 first time
            lsum *= corr;
#pragma unroll
            for (int g = 0; g < 16; ++g) {
                o4[g].x *= corr; o4[g].y *= corr; o4[g].z *= corr; o4[g].w *= corr;
            }
            for (int j = 0; j < 32; ++j) {
                const float p = __expf(sS[r * SS_STRIDE + j] - mnew);
                lsum += p;
#pragma unroll
                for (int g = 0; g < 16; ++g) {
                    const float4 vv = *(const float4*)(sV + j * 256 + (g * 4 + c4) * 4);
                    o4[g].x += p * vv.x; o4[g].y += p * vv.y;
                    o4[g].z += p * vv.z; o4[g].w += p * vv.w;
                }
            }
            mrun = mnew;
        }
    }

    // lsum identical across the 4 lanes of a row (computed from identical s[]).
    // Fully-masked row (qm set, or every key masked) -> lsum==0 -> o = 0,
    // exactly matching the reference's nan->0 semantics.
    const float inv = (lsum > 0.f) ? (1.0f / lsum) : 0.f;

    // ---- epilogue: y = x + ls_gamma * o; LayerNorm over D=256 ----
    const int t = q0 + r;
    const size_t ti = (size_t)(b * Tq + t) * Cq + c;
    const float* xr = x + ti * Dq;

    float sum = 0.f, ssq = 0.f;
#pragma unroll
    for (int g = 0; g < 16; ++g) {
        const int col = (g * 4 + c4) * 4;
        const float4 xv = *(const float4*)(xr + col);
        const float4 gv = *(const float4*)(lsg + col);
        float4 y;
        y.x = xv.x + gv.x * (o4[g].x * inv);
        y.y = xv.y + gv.y * (o4[g].y * inv);
        y.z = xv.z + gv.z * (o4[g].z * inv);
        y.w = xv.w + gv.w * (o4[g].w * inv);
        o4[g] = y;
        sum += y.x + y.y + y.z + y.w;
        ssq += y.x * y.x + y.y * y.y + y.z * y.z + y.w * y.w;
    }
    sum += __shfl_xor_sync(0xffffffffu, sum, 1);
    sum += __shfl_xor_sync(0xffffffffu, sum, 2);
    ssq += __shfl_xor_sync(0xffffffffu, ssq, 1);
    ssq += __shfl_xor_sync(0xffffffffu, ssq, 2);

    const float mu = sum * (1.0f / 256.0f);
    const float var = ssq * (1.0f / 256.0f) - mu * mu;
    const float rstd = rsqrtf(var + 1e-5f);

#pragma unroll
    for (int g = 0; g < 16; ++g) {
        const int col = (g * 4 + c4) * 4;
        const float4 gg = *(const float4*)(lng + col);
        const float4 bb = *(const float4*)(lnb + col);
        const float4 y = o4[g];
        float4 o;
        o.x = (y.x - mu) * rstd * gg.x + bb.x;
        o.y = (y.y - mu) * rstd * gg.y + bb.y;
        o.z = (y.z - mu) * rstd * gg.z + bb.z;
        o.w = (y.w - mu) * rstd * gg.w + bb.w;
        *(float4*)(out + ti * Dq + col) = o;
    }
}

// ---------------------------------------------------------------------------
// Launcher
// inputs: 0 x, 1 x_mask(bool/u8), 2 pos(i32), 3 pe, 4 wq_w, 5 wq_b, 6 wk_w,
//         7 wk_b, 8 wv_w, 9 wv_b, 10 ln_g, 11 ln_b, 12 ls_gamma
// ---------------------------------------------------------------------------
extern "C" void kernel_launch(void* const* d_in, const int* in_sizes, int n_in,
                              void* d_out, int out_size)
{
    const float* x   = (const float*)d_in[0];
    const unsigned char* xmask = (const unsigned char*)d_in[1];
    const int*   pos = (const int*)d_in[2];
    const float* pe  = (const float*)d_in[3];
    const float* wq  = (const float*)d_in[4];
    const float* bq  = (const float*)d_in[5];
    const float* wk  = (const float*)d_in[6];
    const float* bk  = (const float*)d_in[7];
    const float* wv  = (const float*)d_in[8];
    const float* bv  = (const float*)d_in[9];
    const float* lng = (const float*)d_in[10];
    const float* lnb = (const float*)d_in[11];
    const float* lsg = (const float*)d_in[12];
    float* out = (float*)d_out;

    // Kernel 1: QKV + bias + rotation
    dim3 g1(12, MTOT / 64);
    qkv_rope_kernel<<<g1, 256>>>(x, pos, pe, wq, bq, wk, bk, wv, bv);

    // Kernel 2: attention + residual + LN (dynamic smem ~138 KB)
    const int smem_bytes = (64 * SQ_STRIDE + 2 * 32 * 256 + 64 * SS_STRIDE) * 4
                           + (64 + 32) * 4;
    cudaFuncSetAttribute(attn_ln_kernel,
                         cudaFuncAttributeMaxDynamicSharedMemorySize, smem_bytes);
    dim3 g2(Tq / 64, NHEADS);
    attn_ln_kernel<<<g2, 256, smem_bytes>>>(x, xmask, lng, lnb, lsg, out);
}

// round 2
// speedup vs baseline: 6.2302x; 6.2302x over previous
#include <cuda_runtime.h>
#include <cuda_bf16.h>
#include <math_constants.h>
#include <cstdint>

#define Bq 4
#define Tq 1024
#define Cq 16
#define Dq 256
#define NHEADS (Bq*Cq)          // 64
#define MTOT (Bq*Tq*Cq)         // 65536 tokens

// bf16 scratch
__device__ __nv_bfloat16 g_xb[(size_t)MTOT * Dq];            // x in bf16
__device__ __nv_bfloat16 g_wb[3 * Dq * Dq];                  // wq|wk|wv bf16 [n][k]
__device__ __nv_bfloat16 g_q [(size_t)NHEADS * Tq * Dq];     // [h][t][d]
__device__ __nv_bfloat16 g_k [(size_t)NHEADS * Tq * Dq];     // [h][t][d]
__device__ __nv_bfloat16 g_vt[(size_t)NHEADS * Dq * Tq];     // [h][d][t] (transposed)

static __device__ __forceinline__ unsigned pack_bf16(float lo, float hi) {
    __nv_bfloat162 h = __floats2bfloat162_rn(lo, hi);
    return *reinterpret_cast<unsigned*>(&h);
}

static __device__ __forceinline__ void mma_bf16(
    float& d0, float& d1, float& d2, float& d3,
    unsigned a0, unsigned a1, unsigned a2, unsigned a3,
    unsigned b0, unsigned b1)
{
    asm volatile(
        "mma.sync.aligned.m16n8k16.row.col.f32.bf16.bf16.f32 "
        "{%0,%1,%2,%3}, {%4,%5,%6,%7}, {%8,%9}, {%0,%1,%2,%3};\n"
        : "+f"(d0), "+f"(d1), "+f"(d2), "+f"(d3)
        : "r"(a0), "r"(a1), "r"(a2), "r"(a3), "r"(b0), "r"(b1));
}

// ---------------------------------------------------------------------------
// Converters
// ---------------------------------------------------------------------------
__global__ void conv_x_kernel(const float* __restrict__ x)
{
    int i = blockIdx.x * blockDim.x + threadIdx.x;   // float4 index
    const float4 v = ((const float4*)x)[i];
    unsigned lo = pack_bf16(v.x, v.y);
    unsigned hi = pack_bf16(v.z, v.w);
    ((uint2*)g_xb)[i] = make_uint2(lo, hi);
}

__global__ void conv_w_kernel(const float* __restrict__ wq,
                              const float* __restrict__ wk,
                              const float* __restrict__ wv)
{
    int i = blockIdx.x * blockDim.x + threadIdx.x;   // 0..65535
    g_wb[i]           = __float2bfloat16(wq[i]);
    g_wb[i + 65536]   = __float2bfloat16(wk[i]);
    g_wb[i + 131072]  = __float2bfloat16(wv[i]);
}

// ---------------------------------------------------------------------------
// Kernel 1: QKV projection on tensor cores + bias + RoPE, scatter to
// head-major layouts. CTA tile: 128(M) x 64(N), K=256 in one shot.
// 8 warps, warp w owns rows w*16..w*16+15 (all 64 N cols).
// ---------------------------------------------------------------------------
#define XS 264
#define WS 264

__global__ __launch_bounds__(256, 1) void qkv_tc_kernel(
    const int*   __restrict__ pos,
    const float* __restrict__ pe,
    const float* __restrict__ bq,
    const float* __restrict__ bk,
    const float* __restrict__ bv)
{
    extern __shared__ char smraw[];
    __nv_bfloat16* sX = (__nv_bfloat16*)smraw;        // 128 x XS
    __nv_bfloat16* sW = sX + 128 * XS;                // 64 x WS

    const int tid  = threadIdx.x;
    const int w    = tid >> 5;
    const int lane = tid & 31;
    const int q    = lane & 3;
    const int lr   = lane >> 2;

    const int mtile = blockIdx.y;
    const int bx    = blockIdx.x;          // 0..11
    const int mat   = bx >> 2;
    const int n0    = (bx & 3) * 64;
    const int m0    = mtile * 128;

    // load X tile: 128 rows x 256 cols (8192 uint2)
    const __nv_bfloat16* xb = g_xb + (size_t)m0 * Dq;
#pragma unroll
    for (int it = 0; it < 32; ++it) {
        int idx = it * 256 + tid;
        int row = idx >> 6, c4 = idx & 63;
        *(uint2*)&sX[row * XS + c4 * 4] = *(const uint2*)(xb + row * Dq + c4 * 4);
    }
    // load W tile: 64 rows x 256 cols (4096 uint2)
    const __nv_bfloat16* wb = g_wb + mat * 65536 + n0 * Dq;
#pragma unroll
    for (int it = 0; it < 16; ++it) {
        int idx = it * 256 + tid;
        int row = idx >> 6, c4 = idx & 63;
        *(uint2*)&sW[row * WS + c4 * 4] = *(const uint2*)(wb + row * Dq + c4 * 4);
    }
    __syncthreads();

    float acc[8][4];
#pragma unroll
    for (int nf = 0; nf < 8; ++nf)
#pragma unroll
        for (int j = 0; j < 4; ++j) acc[nf][j] = 0.f;

    const int ra = w * 16 + lr;
#pragma unroll
    for (int kk = 0; kk < 16; ++kk) {
        const int kb = kk * 16 + 2 * q;
        unsigned a0 = *(const unsigned*)&sX[ra * XS + kb];
        unsigned a1 = *(const unsigned*)&sX[(ra + 8) * XS + kb];
        unsigned a2 = *(const unsigned*)&sX[ra * XS + kb + 8];
        unsigned a3 = *(const unsigned*)&sX[(ra + 8) * XS + kb + 8];
#pragma unroll
        for (int nf = 0; nf < 8; ++nf) {
            const int br = nf * 8 + lr;
            unsigned b0 = *(const unsigned*)&sW[br * WS + kb];
            unsigned b1 = *(const unsigned*)&sW[br * WS + kb + 8];
            mma_bf16(acc[nf][0], acc[nf][1], acc[nf][2], acc[nf][3],
                     a0, a1, a2, a3, b0, b1);
        }
    }

    // epilogue: bias + RoPE + scatter
    const float* bias = (mat == 0) ? bq : (mat == 1) ? bk : bv;
    const int tokA = m0 + w * 16 + lr;
    const int tokB = tokA + 8;
    const int bA = tokA >> 14, tA = (tokA >> 4) & (Tq - 1), cA = tokA & (Cq - 1);
    const int bB = tokB >> 14, tB = (tokB >> 4) & (Tq - 1), cB = tokB & (Cq - 1);
    const int hA = bA * Cq + cA, hB = bB * Cq + cB;

    int pA = 0, pB = 0;
    if (mat < 2) { pA = pos[tokA]; pB = pos[tokB]; }

    __nv_bfloat16* outq = (mat == 0) ? g_q : g_k;

#pragma unroll
    for (int nf = 0; nf < 8; ++nf) {
        const int c = n0 + nf * 8 + 2 * q;                  // even
        const float2 bb = *(const float2*)(bias + c);
        float v0 = acc[nf][0] + bb.x, v1 = acc[nf][1] + bb.y;   // row A
        float v2 = acc[nf][2] + bb.x, v3 = acc[nf][3] + bb.y;   // row B
        if (mat < 2) {
            const float2 csA = *(const float2*)(pe + (size_t)pA * Dq + c);
            const float2 csB = *(const float2*)(pe + (size_t)pB * Dq + c);
            float r0 = v0 * csA.x - v1 * csA.y;
            float r1 = v0 * csA.y + v1 * csA.x;
            float r2 = v2 * csB.x - v3 * csB.y;
            float r3 = v2 * csB.y + v3 * csB.x;
            *(unsigned*)&outq[((size_t)hA * Tq + tA) * Dq + c] = pack_bf16(r0, r1);
            *(unsigned*)&outq[((size_t)hB * Tq + tB) * Dq + c] = pack_bf16(r2, r3);
        } else {
            g_vt[((size_t)hA * Dq + c)     * Tq + tA] = __float2bfloat16(v0);
            g_vt[((size_t)hA * Dq + c + 1) * Tq + tA] = __float2bfloat16(v1);
            g_vt[((size_t)hB * Dq + c)     * Tq + tB] = __float2bfloat16(v2);
            g_vt[((size_t)hB * Dq + c + 1) * Tq + tB] = __float2bfloat16(v3);
        }
    }
}

// ---------------------------------------------------------------------------
// Kernel 2: flash attention (bf16 HMMA) + residual + LayerScale + LayerNorm.
// CTA = (head h, 128 q-rows). 8 warps, warp owns 16 q-rows.
// K tiles of 64 rows, 16 iterations.
// ---------------------------------------------------------------------------
#define QS 264
#define KS 264
#define VS 72

__global__ __launch_bounds__(256, 1) void attn_tc_kernel(
    const float* __restrict__ x,
    const unsigned char* __restrict__ xmask,
    const float* __restrict__ lng,
    const float* __restrict__ lnb,
    const float* __restrict__ lsg,
    float* __restrict__ out)
{
    extern __shared__ char smraw[];
    __nv_bfloat16* sQ  = (__nv_bfloat16*)smraw;       // 128 x QS
    __nv_bfloat16* sK  = sQ + 128 * QS;               // 64 x KS
    __nv_bfloat16* sVt = sK + 64 * KS;                // 256 x VS
    unsigned char* sQm = (unsigned char*)(sVt + 256 * VS);   // 128
    unsigned char* sKm = sQm + 128;                           // 64

    const int tid  = threadIdx.x;
    const int w    = tid >> 5;
    const int lane = tid & 31;
    const int q    = lane & 3;
    const int lr   = lane >> 2;

    const int h  = blockIdx.y;
    const int b  = h >> 4, c = h & 15;
    const int q0 = blockIdx.x * 128;

    // load Q tile 128x256
    const __nv_bfloat16* qb = g_q + ((size_t)h * Tq + q0) * Dq;
#pragma unroll
    for (int it = 0; it < 32; ++it) {
        int idx = it * 256 + tid;
        int row = idx >> 6, c4 = idx & 63;
        *(uint2*)&sQ[row * QS + c4 * 4] = *(const uint2*)(qb + row * Dq + c4 * 4);
    }
    if (tid < 128) sQm[tid] = xmask[(size_t)(b * Tq + q0 + tid) * Cq + c];
    __syncthreads();

    const int qmA = sQm[w * 16 + lr];
    const int qmB = sQm[w * 16 + lr + 8];

    float oacc[32][4];
#pragma unroll
    for (int nf = 0; nf < 32; ++nf)
#pragma unroll
        for (int j = 0; j < 4; ++j) oacc[nf][j] = 0.f;
    float mrunA = -CUDART_INF_F, mrunB = -CUDART_INF_F;
    float lsumA = 0.f, lsumB = 0.f;

    const __nv_bfloat16* kb = g_k  + (size_t)h * Tq * Dq;
    const __nv_bfloat16* vb = g_vt + (size_t)h * Dq * Tq;

    for (int kt = 0; kt < 16; ++kt) {
        const int k0 = kt * 64;
        __syncthreads();
        // K tile 64x256
#pragma unroll
        for (int it = 0; it < 16; ++it) {
            int idx = it * 256 + tid;
            int row = idx >> 6, c4 = idx & 63;
            *(uint2*)&sK[row * KS + c4 * 4] =
                *(const uint2*)(kb + (size_t)(k0 + row) * Dq + c4 * 4);
        }
        // Vt tile 256x64
#pragma unroll
        for (int it = 0; it < 16; ++it) {
            int idx = it * 256 + tid;
            int row = idx >> 4, c4 = idx & 15;
            *(uint2*)&sVt[row * VS + c4 * 4] =
                *(const uint2*)(vb + (size_t)row * Tq + k0 + c4 * 4);
        }
        if (tid < 64) sKm[tid] = xmask[(size_t)(b * Tq + k0 + tid) * Cq + c];
        __syncthreads();

        // ---- S = Q K^T ----
        float sacc[8][4];
#pragma unroll
        for (int nf = 0; nf < 8; ++nf)
#pragma unroll
            for (int j = 0; j < 4; ++j) sacc[nf][j] = 0.f;

        const int ra = w * 16 + lr;
#pragma unroll
        for (int kk = 0; kk < 16; ++kk) {
            const int kbse = kk * 16 + 2 * q;
            unsigned a0 = *(const unsigned*)&sQ[ra * QS + kbse];
            unsigned a1 = *(const unsigned*)&sQ[(ra + 8) * QS + kbse];
            unsigned a2 = *(const unsigned*)&sQ[ra * QS + kbse + 8];
            unsigned a3 = *(const unsigned*)&sQ[(ra + 8) * QS + kbse + 8];
#pragma unroll
            for (int nf = 0; nf < 8; ++nf) {
                const int br = nf * 8 + lr;
                unsigned b0 = *(const unsigned*)&sK[br * KS + kbse];
                unsigned b1 = *(const unsigned*)&sK[br * KS + kbse + 8];
                mma_bf16(sacc[nf][0], sacc[nf][1], sacc[nf][2], sacc[nf][3],
                         a0, a1, a2, a3, b0, b1);
            }
        }

        // ---- mask + scale + row max ----
        float tmaxA = -CUDART_INF_F, tmaxB = -CUDART_INF_F;
#pragma unroll
        for (int nf = 0; nf < 8; ++nf) {
            const int cc = nf * 8 + 2 * q;
            const int k0m = sKm[cc], k1m = sKm[cc + 1];
            sacc[nf][0] = (qmA | k0m) ? -CUDART_INF_F : sacc[nf][0] * 0.0625f;
            sacc[nf][1] = (qmA | k1m) ? -CUDART_INF_F : sacc[nf][1] * 0.0625f;
            sacc[nf][2] = (qmB | k0m) ? -CUDART_INF_F : sacc[nf][2] * 0.0625f;
            sacc[nf][3] = (qmB | k1m) ? -CUDART_INF_F : sacc[nf][3] * 0.0625f;
            tmaxA = fmaxf(tmaxA, fmaxf(sacc[nf][0], sacc[nf][1]));
            tmaxB = fmaxf(tmaxB, fmaxf(sacc[nf][2], sacc[nf][3]));
        }
        tmaxA = fmaxf(tmaxA, __shfl_xor_sync(0xffffffffu, tmaxA, 1));
        tmaxA = fmaxf(tmaxA, __shfl_xor_sync(0xffffffffu, tmaxA, 2));
        tmaxB = fmaxf(tmaxB, __shfl_xor_sync(0xffffffffu, tmaxB, 1));
        tmaxB = fmaxf(tmaxB, __shfl_xor_sync(0xffffffffu, tmaxB, 2));

        // ---- online softmax ----
        const float mnA = fmaxf(mrunA, tmaxA);
        const float mnB = fmaxf(mrunB, tmaxB);
        const float corrA = (mnA == -CUDART_INF_F) ? 1.f : __expf(mrunA - mnA);
        const float corrB = (mnB == -CUDART_INF_F) ? 1.f : __expf(mrunB - mnB);
        const float mUA = (mnA == -CUDART_INF_F) ? 0.f : mnA;
        const float mUB = (mnB == -CUDART_INF_F) ? 0.f : mnB;
        lsumA *= corrA;
        lsumB *= corrB;
        mrunA = mnA; mrunB = mnB;

        unsigned pa[4][4];
#pragma unroll
        for (int kk = 0; kk < 4; ++kk) {
            float p00 = __expf(sacc[2*kk][0]   - mUA);
            float p01 = __expf(sacc[2*kk][1]   - mUA);
            float p02 = __expf(sacc[2*kk][2]   - mUB);
            float p03 = __expf(sacc[2*kk][3]   - mUB);
            float p10 = __expf(sacc[2*kk+1][0] - mUA);
            float p11 = __expf(sacc[2*kk+1][1] - mUA);
            float p12 = __expf(sacc[2*kk+1][2] - mUB);
            float p13 = __expf(sacc[2*kk+1][3] - mUB);
            lsumA += p00 + p01 + p10 + p11;
            lsumB += p02 + p03 + p12 + p13;
            pa[kk][0] = pack_bf16(p00, p01);
            pa[kk][1] = pack_bf16(p02, p03);
            pa[kk][2] = pack_bf16(p10, p11);
            pa[kk][3] = pack_bf16(p12, p13);
        }

        // rescale O
#pragma unroll
        for (int nf = 0; nf < 32; ++nf) {
            oacc[nf][0] *= corrA; oacc[nf][1] *= corrA;
            oacc[nf][2] *= corrB; oacc[nf][3] *= corrB;
        }

        // ---- O += P V ----
#pragma unroll
        for (int nf = 0; nf < 32; ++nf) {
            const int vr = nf * 8 + lr;
#pragma unroll
            for (int kk = 0; kk < 4; ++kk) {
                const int kbse = kk * 16 + 2 * q;
                unsigned b0 = *(const unsigned*)&sVt[vr * VS + kbse];
                unsigned b1 = *(const unsigned*)&sVt[vr * VS + kbse + 8];
                mma_bf16(oacc[nf][0], oacc[nf][1], oacc[nf][2], oacc[nf][3],
                         pa[kk][0], pa[kk][1], pa[kk][2], pa[kk][3], b0, b1);
            }
        }
    }

    // ---- epilogue ----
    lsumA += __shfl_xor_sync(0xffffffffu, lsumA, 1);
    lsumA += __shfl_xor_sync(0xffffffffu, lsumA, 2);
    lsumB += __shfl_xor_sync(0xffffffffu, lsumB, 1);
    lsumB += __shfl_xor_sync(0xffffffffu, lsumB, 2);
    const float invA = (lsumA > 0.f) ? (1.f / lsumA) : 0.f;
    const float invB = (lsumB > 0.f) ? (1.f / lsumB) : 0.f;

    const int gtA = q0 + w * 16 + lr;
    const int gtB = gtA + 8;
    const size_t miA = (size_t)(b * Tq + gtA) * Cq + c;
    const size_t miB = (size_t)(b * Tq + gtB) * Cq + c;
    const float* xA = x + miA * Dq;
    const float* xB = x + miB * Dq;

    float sumA = 0.f, ssqA = 0.f, sumB = 0.f, ssqB = 0.f;
#pragma unroll
    for (int nf = 0; nf < 32; ++nf) {
        const int cc = nf * 8 + 2 * q;
        const float2 g2 = *(const float2*)(lsg + cc);
        const float2 xa = *(const float2*)(xA + cc);
        const float2 xb2 = *(const float2*)(xB + cc);
        float y0 = xa.x  + g2.x * (oacc[nf][0] * invA);
        float y1 = xa.y  + g2.y * (oacc[nf][1] * invA);
        float y2 = xb2.x + g2.x * (oacc[nf][2] * invB);
        float y3 = xb2.y + g2.y * (oacc[nf][3] * invB);
        oacc[nf][0] = y0; oacc[nf][1] = y1; oacc[nf][2] = y2; oacc[nf][3] = y3;
        sumA += y0 + y1;        ssqA += y0 * y0 + y1 * y1;
        sumB += y2 + y3;        ssqB += y2 * y2 + y3 * y3;
    }
    sumA += __shfl_xor_sync(0xffffffffu, sumA, 1);
    sumA += __shfl_xor_sync(0xffffffffu, sumA, 2);
    ssqA += __shfl_xor_sync(0xffffffffu, ssqA, 1);
    ssqA += __shfl_xor_sync(0xffffffffu, ssqA, 2);
    sumB += __shfl_xor_sync(0xffffffffu, sumB, 1);
    sumB += __shfl_xor_sync(0xffffffffu, sumB, 2);
    ssqB += __shfl_xor_sync(0xffffffffu, ssqB, 1);
    ssqB += __shfl_xor_sync(0xffffffffu, ssqB, 2);

    const float muA = sumA * (1.f / 256.f);
    const float muB = sumB * (1.f / 256.f);
    const float rsA = rsqrtf(ssqA * (1.f / 256.f) - muA * muA + 1e-5f);
    const float rsB = rsqrtf(ssqB * (1.f / 256.f) - muB * muB + 1e-5f);

    float* oA = out + miA * Dq;
    float* oB = out + miB * Dq;
#pragma unroll
    for (int nf = 0; nf < 32; ++nf) {
        const int cc = nf * 8 + 2 * q;
        const float2 gg = *(const float2*)(lng + cc);
        const float2 bb = *(const float2*)(lnb + cc);
        float2 r0, r1;
        r0.x = (oacc[nf][0] - muA) * rsA * gg.x + bb.x;
        r0.y = (oacc[nf][1] - muA) * rsA * gg.y + bb.y;
        r1.x = (oacc[nf][2] - muB) * rsB * gg.x + bb.x;
        r1.y = (oacc[nf][3] - muB) * rsB * gg.y + bb.y;
        *(float2*)(oA + cc) = r0;
        *(float2*)(oB + cc) = r1;
    }
}

// ---------------------------------------------------------------------------
// Launcher. Inputs: 0 x, 1 x_mask(u8), 2 pos(i32), 3 pe, 4 wq_w, 5 wq_b,
// 6 wk_w, 7 wk_b, 8 wv_w, 9 wv_b, 10 ln_g, 11 ln_b, 12 ls_gamma
// ---------------------------------------------------------------------------
extern "C" void kernel_launch(void* const* d_in, const int* in_sizes, int n_in,
                              void* d_out, int out_size)
{
    const float* x   = (const float*)d_in[0];
    const unsigned char* xmask = (const unsigned char*)d_in[1];
    const int*   pos = (const int*)d_in[2];
    const float* pe  = (const float*)d_in[3];
    const float* wq  = (const float*)d_in[4];
    const float* bq  = (const float*)d_in[5];
    const float* wk  = (const float*)d_in[6];
    const float* bk  = (const float*)d_in[7];
    const float* wv  = (const float*)d_in[8];
    const float* bv  = (const float*)d_in[9];
    const float* lng = (const float*)d_in[10];
    const float* lnb = (const float*)d_in[11];
    const float* lsg = (const float*)d_in[12];
    float* out = (float*)d_out;

    // converts
    conv_x_kernel<<<(MTOT * Dq / 4) / 256, 256>>>(x);
    conv_w_kernel<<<(Dq * Dq) / 256, 256>>>(wq, wk, wv);

    // QKV projection (tensor cores)
    const int smem1 = (128 * XS + 64 * WS) * 2;
    cudaFuncSetAttribute(qkv_tc_kernel,
                         cudaFuncAttributeMaxDynamicSharedMemorySize, smem1);
    qkv_tc_kernel<<<dim3(12, MTOT / 128), 256, smem1>>>(pos, pe, bq, bk, bv);

    // attention + LN (tensor cores)
    const int smem2 = (128 * QS + 64 * KS + 256 * VS) * 2 + 192;
    cudaFuncSetAttribute(attn_tc_kernel,
                         cudaFuncAttributeMaxDynamicSharedMemorySize, smem2);
    attn_tc_kernel<<<dim3(Tq / 128, NHEADS), 256, smem2>>>(
        x, xmask, lng, lnb, lsg, out);
}

// round 3
// speedup vs baseline: 10.7108x; 1.7192x over previous
#include <cuda_runtime.h>
#include <cuda_fp16.h>
#include <math_constants.h>
#include <cstdint>

#define Bq 4
#define Tq 1024
#define Cq 16
#define Dq 256
#define NHEADS (Bq*Cq)          // 64
#define MTOT (Bq*Tq*Cq)         // 65536 tokens

// f16 scratch
__device__ __align__(128) __half g_xb[(size_t)MTOT * Dq];
__device__ __align__(128) __half g_wb[3 * Dq * Dq];              // wq|wk|wv [n][k]
__device__ __align__(128) __half g_q [(size_t)NHEADS * Tq * Dq]; // [h][t][d]
__device__ __align__(128) __half g_k [(size_t)NHEADS * Tq * Dq]; // [h][t][d]
__device__ __align__(128) __half g_v [(size_t)NHEADS * Tq * Dq]; // [h][t][d]
__device__ __align__(128) unsigned char g_mt[NHEADS * Tq];       // mask [h][t]

// ---------------------------------------------------------------------------
// helpers
// ---------------------------------------------------------------------------
static __device__ __forceinline__ unsigned packh(float a, float b) {
    __half2 h = __floats2half2_rn(a, b);
    return *reinterpret_cast<unsigned*>(&h);
}
static __device__ __forceinline__ float2 unph(unsigned u) {
    __half2 h = *reinterpret_cast<__half2*>(&u);
    return __half22float2(h);
}
static __device__ __forceinline__ unsigned hmul2u(unsigned a, unsigned b) {
    __half2 r = __hmul2(*reinterpret_cast<__half2*>(&a),
                        *reinterpret_cast<__half2*>(&b));
    return *reinterpret_cast<unsigned*>(&r);
}

static __device__ __forceinline__ void mma_f16_f32(
    float& d0, float& d1, float& d2, float& d3,
    unsigned a0, unsigned a1, unsigned a2, unsigned a3,
    unsigned b0, unsigned b1)
{
    asm volatile(
        "mma.sync.aligned.m16n8k16.row.col.f32.f16.f16.f32 "
        "{%0,%1,%2,%3}, {%4,%5,%6,%7}, {%8,%9}, {%0,%1,%2,%3};\n"
        : "+f"(d0), "+f"(d1), "+f"(d2), "+f"(d3)
        : "r"(a0), "r"(a1), "r"(a2), "r"(a3), "r"(b0), "r"(b1));
}
static __device__ __forceinline__ void mma_f16_f16(
    unsigned& d0, unsigned& d1,
    unsigned a0, unsigned a1, unsigned a2, unsigned a3,
    unsigned b0, unsigned b1)
{
    asm volatile(
        "mma.sync.aligned.m16n8k16.row.col.f16.f16.f16.f16 "
        "{%0,%1}, {%2,%3,%4,%5}, {%6,%7}, {%0,%1};\n"
        : "+r"(d0), "+r"(d1)
        : "r"(a0), "r"(a1), "r"(a2), "r"(a3), "r"(b0), "r"(b1));
}
static __device__ __forceinline__ void ldsm_x4(
    unsigned& r0, unsigned& r1, unsigned& r2, unsigned& r3, unsigned addr)
{
    asm volatile("ldmatrix.sync.aligned.m8n8.x4.shared.b16 {%0,%1,%2,%3}, [%4];"
        : "=r"(r0), "=r"(r1), "=r"(r2), "=r"(r3) : "r"(addr));
}
static __device__ __forceinline__ void ldsm_x4_t(
    unsigned& r0, unsigned& r1, unsigned& r2, unsigned& r3, unsigned addr)
{
    asm volatile("ldmatrix.sync.aligned.m8n8.x4.trans.shared.b16 {%0,%1,%2,%3}, [%4];"
        : "=r"(r0), "=r"(r1), "=r"(r2), "=r"(r3) : "r"(addr));
}

#define CPA16(d, s) asm volatile("cp.async.cg.shared.global [%0], [%1], 16;" :: "r"(d), "l"(s))
#define CP_COMMIT() asm volatile("cp.async.commit_group;")
#define CP_WAIT(n)  asm volatile("cp.async.wait_group %0;" :: "n"(n))

// ---------------------------------------------------------------------------
// Converters
// ---------------------------------------------------------------------------
__global__ void conv_x_kernel(const float* __restrict__ x)
{
    int i = blockIdx.x * blockDim.x + threadIdx.x;   // float4 index
    const float4 v = ((const float4*)x)[i];
    ((uint2*)g_xb)[i] = make_uint2(packh(v.x, v.y), packh(v.z, v.w));
}
__global__ void conv_w_kernel(const float* __restrict__ wq,
                              const float* __restrict__ wk,
                              const float* __restrict__ wv)
{
    int i = blockIdx.x * blockDim.x + threadIdx.x;   // 0..65535
    g_wb[i]          = __float2half(wq[i]);
    g_wb[i + 65536]  = __float2half(wk[i]);
    g_wb[i + 131072] = __float2half(wv[i]);
}
__global__ void conv_m_kernel(const unsigned char* __restrict__ xmask)
{
    int i = blockIdx.x * blockDim.x + threadIdx.x;   // 0..65535
    int h = i >> 10, t = i & 1023;
    int b = h >> 4,  c = h & 15;
    g_mt[i] = xmask[(size_t)((b << 10) + t) * Cq + c];
}

// ---------------------------------------------------------------------------
// Kernel 1: QKV projection (f16 HMMA, f32 accum) + bias + RoPE.
// CTA tile 128(M) x 64(N), K=256. All outputs stored coalesced [h][t][d].
// ---------------------------------------------------------------------------
#define XS 264
#define WS 264

__global__ __launch_bounds__(256, 1) void qkv_tc_kernel(
    const int*   __restrict__ pos,
    const float* __restrict__ pe,
    const float* __restrict__ bq,
    const float* __restrict__ bk,
    const float* __restrict__ bv)
{
    extern __shared__ char smraw[];
    __half* sX = (__half*)smraw;          // 128 x XS
    __half* sW = sX + 128 * XS;           // 64 x WS

    const int tid  = threadIdx.x;
    const int w    = tid >> 5;
    const int lane = tid & 31;
    const int q    = lane & 3;
    const int lr   = lane >> 2;

    const int mtile = blockIdx.y;
    const int bx    = blockIdx.x;          // 0..11
    const int mat   = bx >> 2;
    const int n0    = (bx & 3) * 64;
    const int m0    = mtile * 128;

    const __half* xb = g_xb + (size_t)m0 * Dq;
#pragma unroll
    for (int it = 0; it < 32; ++it) {
        int idx = it * 256 + tid;
        int row = idx >> 6, c4 = idx & 63;
        *(uint2*)&sX[row * XS + c4 * 4] = *(const uint2*)(xb + row * Dq + c4 * 4);
    }
    const __half* wb = g_wb + mat * 65536 + n0 * Dq;
#pragma unroll
    for (int it = 0; it < 16; ++it) {
        int idx = it * 256 + tid;
        int row = idx >> 6, c4 = idx & 63;
        *(uint2*)&sW[row * WS + c4 * 4] = *(const uint2*)(wb + row * Dq + c4 * 4);
    }
    __syncthreads();

    float acc[8][4];
#pragma unroll
    for (int nf = 0; nf < 8; ++nf)
#pragma unroll
        for (int j = 0; j < 4; ++j) acc[nf][j] = 0.f;

    const int g  = lane >> 3;
    const int r8 = lane & 7;
    unsigned smem_u = (unsigned)__cvta_generic_to_shared(smraw);
    // A frags via ldmatrix: rows = m, cols = k
    const unsigned qa_off = smem_u +
        ((unsigned)(w * 16 + (g & 1) * 8 + r8) * XS + (g >> 1) * 8) * 2;
    // B frags via ldmatrix: rows = n, cols = k
    const unsigned kb_off = smem_u + 128 * XS * 2 +
        ((unsigned)((g >> 1) * 8 + r8) * WS + (g & 1) * 8) * 2;

#pragma unroll
    for (int kk = 0; kk < 16; ++kk) {
        unsigned a0, a1, a2, a3;
        ldsm_x4(a0, a1, a2, a3, qa_off + kk * 32);
#pragma unroll
        for (int ng = 0; ng < 4; ++ng) {
            unsigned b0, b1, b2, b3;
            ldsm_x4(b0, b1, b2, b3, kb_off + ng * 16 * WS * 2 + kk * 32);
            mma_f16_f32(acc[2*ng][0], acc[2*ng][1], acc[2*ng][2], acc[2*ng][3],
                        a0, a1, a2, a3, b0, b1);
            mma_f16_f32(acc[2*ng+1][0], acc[2*ng+1][1], acc[2*ng+1][2], acc[2*ng+1][3],
                        a0, a1, a2, a3, b2, b3);
        }
    }

    const float* bias = (mat == 0) ? bq : (mat == 1) ? bk : bv;
    const int tokA = m0 + w * 16 + lr;
    const int tokB = tokA + 8;
    const int bA = tokA >> 14, tA = (tokA >> 4) & (Tq - 1), cA = tokA & (Cq - 1);
    const int bB = tokB >> 14, tB = (tokB >> 4) & (Tq - 1), cB = tokB & (Cq - 1);
    const int hA = bA * Cq + cA, hB = bB * Cq + cB;

    int pA = 0, pB = 0;
    if (mat < 2) { pA = pos[tokA]; pB = pos[tokB]; }

    __half* outp = (mat == 0) ? g_q : (mat == 1) ? g_k : g_v;

#pragma unroll
    for (int nf = 0; nf < 8; ++nf) {
        const int c = n0 + nf * 8 + 2 * q;                  // even
        const float2 bb = *(const float2*)(bias + c);
        float v0 = acc[nf][0] + bb.x, v1 = acc[nf][1] + bb.y;   // row A
        float v2 = acc[nf][2] + bb.x, v3 = acc[nf][3] + bb.y;   // row B
        if (mat < 2) {
            const float2 csA = *(const float2*)(pe + (size_t)pA * Dq + c);
            const float2 csB = *(const float2*)(pe + (size_t)pB * Dq + c);
            float r0 = v0 * csA.x - v1 * csA.y;
            float r1 = v0 * csA.y + v1 * csA.x;
            float r2 = v2 * csB.x - v3 * csB.y;
            float r3 = v2 * csB.y + v3 * csB.x;
            v0 = r0; v1 = r1; v2 = r2; v3 = r3;
        }
        *(unsigned*)&outp[((size_t)hA * Tq + tA) * Dq + c] = packh(v0, v1);
        *(unsigned*)&outp[((size_t)hB * Tq + tB) * Dq + c] = packh(v2, v3);
    }
}

// ---------------------------------------------------------------------------
// Kernel 2: flash attention, f16 HMMA with f16 accumulators, Q frags in
// registers, ldmatrix fragment loads, 2-stage cp.async K/V pipeline,
// fused residual + LayerScale + LayerNorm epilogue.
// CTA = (head, 128 q-rows); 8 warps x 16 q-rows; K-tiles of 64, 16 iters.
// ---------------------------------------------------------------------------
#define STR 264
#define KBYTES (64 * STR * 2)      // 33792 one K (or V) tile
#define STAGEB (2 * KBYTES)        // 67584 per stage

__global__ __launch_bounds__(256, 1) void attn_tc_kernel(
    const float* __restrict__ x,
    const float* __restrict__ lng,
    const float* __restrict__ lnb,
    const float* __restrict__ lsg,
    float* __restrict__ out)
{
    extern __shared__ char smraw[];
    unsigned char* sQm = (unsigned char*)(smraw + 2 * STAGEB);   // 128
    unsigned char* sKm = sQm + 128;                               // 2 x 64
    const unsigned smem_u = (unsigned)__cvta_generic_to_shared(smraw);
    const unsigned sqm_u  = smem_u + 2 * STAGEB;
    const unsigned skm_u  = sqm_u + 128;

    const int tid  = threadIdx.x;
    const int w    = tid >> 5;
    const int lane = tid & 31;
    const int q    = lane & 3;
    const int lr   = lane >> 2;
    const int g    = lane >> 3;
    const int r8   = lane & 7;

    const int h  = blockIdx.y;
    const int b  = h >> 4, c = h & 15;
    const int q0 = blockIdx.x * 128;

    const __half* qg = g_q + ((size_t)h * Tq + q0) * Dq;
    const __half* kg = g_k + (size_t)h * Tq * Dq;
    const __half* vg = g_v + (size_t)h * Tq * Dq;
    const unsigned char* mg = g_mt + h * Tq;

    // ---- stage Q (128x256) into stage-1 region, plus q-mask ----
    const unsigned qs = smem_u + STAGEB;
#pragma unroll
    for (int it = 0; it < 16; ++it) {
        int idx = it * 256 + tid;
        int row = idx >> 5, cc = idx & 31;
        CPA16(qs + (unsigned)(row * STR * 2 + cc * 16), qg + row * Dq + cc * 8);
    }
    if (tid < 8) CPA16(sqm_u + tid * 16, mg + q0 + tid * 16);
    CP_COMMIT();
    CP_WAIT(0);
    __syncthreads();

    // ---- Q fragments -> registers (16 k-groups x 4 regs) ----
    unsigned qf[16][4];
    const unsigned qa_off = qs +
        ((unsigned)(w * 16 + (g & 1) * 8 + r8) * STR + (g >> 1) * 8) * 2;
#pragma unroll
    for (int kk = 0; kk < 16; ++kk)
        ldsm_x4(qf[kk][0], qf[kk][1], qf[kk][2], qf[kk][3], qa_off + kk * 32);
    const int qmA = sQm[w * 16 + lr];
    const int qmB = sQm[w * 16 + lr + 8];
    __syncthreads();   // all warps done with stage-1 region

    // ---- issue kt=0, kt=1 ----
    auto issue = [&](int kt) {
        const int stage = kt & 1;
        const unsigned sb = smem_u + stage * STAGEB;
        const int k0 = kt * 64;
#pragma unroll
        for (int it = 0; it < 8; ++it) {
            int idx = it * 256 + tid;
            int row = idx >> 5, cc = idx & 31;
            CPA16(sb + (unsigned)(row * STR * 2 + cc * 16),
                  kg + (size_t)(k0 + row) * Dq + cc * 8);
            CPA16(sb + KBYTES + (unsigned)(row * STR * 2 + cc * 16),
                  vg + (size_t)(k0 + row) * Dq + cc * 8);
        }
        if (tid < 4) CPA16(skm_u + stage * 64 + tid * 16, mg + k0 + tid * 16);
    };
    issue(0); CP_COMMIT();
    issue(1); CP_COMMIT();

    // fragment lane offsets
    const unsigned koff = ((unsigned)((g >> 1) * 8 + r8) * STR + (g & 1) * 8) * 2;
    const unsigned voff = ((unsigned)((g & 1) * 8 + r8) * STR + (g >> 1) * 8) * 2;

    unsigned oacc[32][2];
#pragma unroll
    for (int j = 0; j < 32; ++j) { oacc[j][0] = 0u; oacc[j][1] = 0u; }
    float mrunA = -CUDART_INF_F, mrunB = -CUDART_INF_F;
    float lsumA = 0.f, lsumB = 0.f;

    for (int kt = 0; kt < 16; ++kt) {
        CP_WAIT(1);
        __syncthreads();
        const int stage = kt & 1;
        const unsigned kb_s = smem_u + stage * STAGEB;
        const unsigned vb_s = kb_s + KBYTES;
        const unsigned char* km = sKm + stage * 64;

        // ---- S = Q K^T (f16 accum) ----
        unsigned sacc[8][2];
#pragma unroll
        for (int nf = 0; nf < 8; ++nf) { sacc[nf][0] = 0u; sacc[nf][1] = 0u; }
#pragma unroll
        for (int kk = 0; kk < 16; ++kk) {
#pragma unroll
            for (int ng = 0; ng < 4; ++ng) {
                unsigned b0, b1, b2, b3;
                ldsm_x4(b0, b1, b2, b3,
                        kb_s + (unsigned)(ng * 16 * STR * 2) + kk * 32 + koff);
                mma_f16_f16(sacc[2*ng][0],   sacc[2*ng][1],
                            qf[kk][0], qf[kk][1], qf[kk][2], qf[kk][3], b0, b1);
                mma_f16_f16(sacc[2*ng+1][0], sacc[2*ng+1][1],
                            qf[kk][0], qf[kk][1], qf[kk][2], qf[kk][3], b2, b3);
            }
        }

        // ---- mask + scale + row max ----
        float sv[8][4];
        float tmaxA = -CUDART_INF_F, tmaxB = -CUDART_INF_F;
#pragma unroll
        for (int nf = 0; nf < 8; ++nf) {
            const float2 lo = unph(sacc[nf][0]);   // row lr
            const float2 hi = unph(sacc[nf][1]);   // row lr+8
            const int cc = nf * 8 + 2 * q;
            const int k0m = km[cc], k1m = km[cc + 1];
            sv[nf][0] = (qmA | k0m) ? -CUDART_INF_F : lo.x * 0.0625f;
            sv[nf][1] = (qmA | k1m) ? -CUDART_INF_F : lo.y * 0.0625f;
            sv[nf][2] = (qmB | k0m) ? -CUDART_INF_F : hi.x * 0.0625f;
            sv[nf][3] = (qmB | k1m) ? -CUDART_INF_F : hi.y * 0.0625f;
            tmaxA = fmaxf(tmaxA, fmaxf(sv[nf][0], sv[nf][1]));
            tmaxB = fmaxf(tmaxB, fmaxf(sv[nf][2], sv[nf][3]));
        }
        tmaxA = fmaxf(tmaxA, __shfl_xor_sync(0xffffffffu, tmaxA, 1));
        tmaxA = fmaxf(tmaxA, __shfl_xor_sync(0xffffffffu, tmaxA, 2));
        tmaxB = fmaxf(tmaxB, __shfl_xor_sync(0xffffffffu, tmaxB, 1));
        tmaxB = fmaxf(tmaxB, __shfl_xor_sync(0xffffffffu, tmaxB, 2));

        const float mnA = fmaxf(mrunA, tmaxA);
        const float mnB = fmaxf(mrunB, tmaxB);
        const float corrA = (mnA == -CUDART_INF_F) ? 1.f : __expf(mrunA - mnA);
        const float corrB = (mnB == -CUDART_INF_F) ? 1.f : __expf(mrunB - mnB);
        const float mUA = (mnA == -CUDART_INF_F) ? 0.f : mnA;
        const float mUB = (mnB == -CUDART_INF_F) ? 0.f : mnB;
        lsumA *= corrA; lsumB *= corrB;
        mrunA = mnA; mrunB = mnB;

        unsigned pa[4][4];
#pragma unroll
        for (int kk = 0; kk < 4; ++kk) {
            float p00 = __expf(sv[2*kk][0]   - mUA);
            float p01 = __expf(sv[2*kk][1]   - mUA);
            float p02 = __expf(sv[2*kk][2]   - mUB);
            float p03 = __expf(sv[2*kk][3]   - mUB);
            float p10 = __expf(sv[2*kk+1][0] - mUA);
            float p11 = __expf(sv[2*kk+1][1] - mUA);
            float p12 = __expf(sv[2*kk+1][2] - mUB);
            float p13 = __expf(sv[2*kk+1][3] - mUB);
            lsumA += p00 + p01 + p10 + p11;
            lsumB += p02 + p03 + p12 + p13;
            pa[kk][0] = packh(p00, p01);
            pa[kk][1] = packh(p02, p03);
            pa[kk][2] = packh(p10, p11);
            pa[kk][3] = packh(p12, p13);
        }

        // rescale O (half2)
        const unsigned cA2 = packh(corrA, corrA);
        const unsigned cB2 = packh(corrB, corrB);
#pragma unroll
        for (int j = 0; j < 32; ++j) {
            oacc[j][0] = hmul2u(oacc[j][0], cA2);
            oacc[j][1] = hmul2u(oacc[j][1], cB2);
        }

        // ---- O += P V  (V frags via ldmatrix.trans) ----
#pragma unroll
        for (int kk = 0; kk < 4; ++kk) {
#pragma unroll
            for (int dg = 0; dg < 16; ++dg) {
                unsigned v0, v1, v2, v3;
                ldsm_x4_t(v0, v1, v2, v3,
                          vb_s + (unsigned)(kk * 16 * STR * 2) + dg * 32 + voff);
                mma_f16_f16(oacc[2*dg][0],   oacc[2*dg][1],
                            pa[kk][0], pa[kk][1], pa[kk][2], pa[kk][3], v0, v1);
                mma_f16_f16(oacc[2*dg+1][0], oacc[2*dg+1][1],
                            pa[kk][0], pa[kk][1], pa[kk][2], pa[kk][3], v2, v3);
            }
        }
        __syncthreads();
        if (kt + 2 < 16) issue(kt + 2);
        CP_COMMIT();
    }

    // ---- epilogue ----
    lsumA += __shfl_xor_sync(0xffffffffu, lsumA, 1);
    lsumA += __shfl_xor_sync(0xffffffffu, lsumA, 2);
    lsumB += __shfl_xor_sync(0xffffffffu, lsumB, 1);
    lsumB += __shfl_xor_sync(0xffffffffu, lsumB, 2);
    const float invA = (lsumA > 0.f) ? (1.f / lsumA) : 0.f;
    const float invB = (lsumB > 0.f) ? (1.f / lsumB) : 0.f;

    const int gtA = q0 + w * 16 + lr;
    const int gtB = gtA + 8;
    const size_t miA = (size_t)(b * Tq + gtA) * Cq + c;
    const size_t miB = (size_t)(b * Tq + gtB) * Cq + c;
    const float* xA = x + miA * Dq;
    const float* xB = x + miB * Dq;

    float yv[32][4];
    float sumA = 0.f, ssqA = 0.f, sumB = 0.f, ssqB = 0.f;
#pragma unroll
    for (int j = 0; j < 32; ++j) {
        const int cc = j * 8 + 2 * q;
        const float2 g2 = *(const float2*)(lsg + cc);
        const float2 xa = *(const float2*)(xA + cc);
        const float2 xb2 = *(const float2*)(xB + cc);
        const float2 oa = unph(oacc[j][0]);
        const float2 ob = unph(oacc[j][1]);
        float y0 = xa.x  + g2.x * (oa.x * invA);
        float y1 = xa.y  + g2.y * (oa.y * invA);
        float y2 = xb2.x + g2.x * (ob.x * invB);
        float y3 = xb2.y + g2.y * (ob.y * invB);
        yv[j][0] = y0; yv[j][1] = y1; yv[j][2] = y2; yv[j][3] = y3;
        sumA += y0 + y1;  ssqA += y0 * y0 + y1 * y1;
        sumB += y2 + y3;  ssqB += y2 * y2 + y3 * y3;
    }
    sumA += __shfl_xor_sync(0xffffffffu, sumA, 1);
    sumA += __shfl_xor_sync(0xffffffffu, sumA, 2);
    ssqA += __shfl_xor_sync(0xffffffffu, ssqA, 1);
    ssqA += __shfl_xor_sync(0xffffffffu, ssqA, 2);
    sumB += __shfl_xor_sync(0xffffffffu, sumB, 1);
    sumB += __shfl_xor_sync(0xffffffffu, sumB, 2);
    ssqB += __shfl_xor_sync(0xffffffffu, ssqB, 1);
    ssqB += __shfl_xor_sync(0xffffffffu, ssqB, 2);

    const float muA = sumA * (1.f / 256.f);
    const float muB = sumB * (1.f / 256.f);
    const float rsA = rsqrtf(ssqA * (1.f / 256.f) - muA * muA + 1e-5f);
    const float rsB = rsqrtf(ssqB * (1.f / 256.f) - muB * muB + 1e-5f);

    float* oA = out + miA * Dq;
    float* oB = out + miB * Dq;
#pragma unroll
    for (int j = 0; j < 32; ++j) {
        const int cc = j * 8 + 2 * q;
        const float2 gg = *(const float2*)(lng + cc);
        const float2 bb = *(const float2*)(lnb + cc);
        float2 r0, r1;
        r0.x = (yv[j][0] - muA) * rsA * gg.x + bb.x;
        r0.y = (yv[j][1] - muA) * rsA * gg.y + bb.y;
        r1.x = (yv[j][2] - muB) * rsB * gg.x + bb.x;
        r1.y = (yv[j][3] - muB) * rsB * gg.y + bb.y;
        *(float2*)(oA + cc) = r0;
        *(float2*)(oB + cc) = r1;
    }
}

// ---------------------------------------------------------------------------
// Launcher. Inputs: 0 x, 1 x_mask(u8), 2 pos(i32), 3 pe, 4 wq_w, 5 wq_b,
// 6 wk_w, 7 wk_b, 8 wv_w, 9 wv_b, 10 ln_g, 11 ln_b, 12 ls_gamma
// ---------------------------------------------------------------------------
extern "C" void kernel_launch(void* const* d_in, const int* in_sizes, int n_in,
                              void* d_out, int out_size)
{
    const float* x   = (const float*)d_in[0];
    const unsigned char* xmask = (const unsigned char*)d_in[1];
    const int*   pos = (const int*)d_in[2];
    const float* pe  = (const float*)d_in[3];
    const float* wq  = (const float*)d_in[4];
    const float* bq  = (const float*)d_in[5];
    const float* wk  = (const float*)d_in[6];
    const float* bk  = (const float*)d_in[7];
    const float* wv  = (const float*)d_in[8];
    const float* bv  = (const float*)d_in[9];
    const float* lng = (const float*)d_in[10];
    const float* lnb = (const float*)d_in[11];
    const float* lsg = (const float*)d_in[12];
    float* out = (float*)d_out;

    conv_x_kernel<<<(MTOT * Dq / 4) / 256, 256>>>(x);
    conv_w_kernel<<<(Dq * Dq) / 256, 256>>>(wq, wk, wv);
    conv_m_kernel<<<(NHEADS * Tq) / 256, 256>>>(xmask);

    const int smem1 = (128 * XS + 64 * WS) * 2;
    cudaFuncSetAttribute(qkv_tc_kernel,
                         cudaFuncAttributeMaxDynamicSharedMemorySize, smem1);
    qkv_tc_kernel<<<dim3(12, MTOT / 128), 256, smem1>>>(pos, pe, bq, bk, bv);

    const int smem2 = 2 * STAGEB + 256;
    cudaFuncSetAttribute(attn_tc_kernel,
                         cudaFuncAttributeMaxDynamicSharedMemorySize, smem2);
    attn_tc_kernel<<<dim3(Tq / 128, NHEADS), 256, smem2>>>(
        x, lng, lnb, lsg, out);
}